// round 14
// baseline (speedup 1.0000x reference)
#include <cuda_runtime.h>
#include <cuda_bf16.h>
#include <cstdint>

#define THREADS 256
#define NCHUNK  64    // per-CTA K = 4096, chunk = 64 fp32 (split-K = 2)

__device__ __align__(256) float g_x32[128 * 8192];      // tf32-rounded x
__device__ __align__(256) float g_part[2 * 128 * 8192]; // split-K partials

__device__ __forceinline__ uint32_t smem_u32(const void* p) {
    uint32_t a;
    asm("{ .reg .u64 t; cvta.to.shared.u64 t, %1; cvt.u32.u64 %0, t; }" : "=r"(a) : "l"(p));
    return a;
}
__device__ __forceinline__ int sign_neg(int a, int b) {  // 1 if e_a*e_b negative
    int t = a >> 1, c = 0;
    while (t) { c += __popc(t & b); t >>= 1; }
    return c & 1;
}
__device__ __forceinline__ void ldsm4(uint32_t& r0, uint32_t& r1, uint32_t& r2, uint32_t& r3,
                                      uint32_t addr) {
    asm volatile("ldmatrix.sync.aligned.m8n8.x4.shared.b16 {%0,%1,%2,%3}, [%4];"
                 : "=r"(r0), "=r"(r1), "=r"(r2), "=r"(r3) : "r"(addr));
}
// a[] in ldsm matrix order {m0,m1,m2,m3}; mma wants {m0,m2,m1,m3}
__device__ __forceinline__ void mma_tf32(float* d, const uint32_t* a, const uint32_t* b) {
    asm volatile(
        "mma.sync.aligned.m16n8k8.row.col.f32.tf32.tf32.f32 "
        "{%0,%1,%2,%3}, {%4,%5,%6,%7}, {%8,%9}, {%0,%1,%2,%3};"
        : "+f"(d[0]), "+f"(d[1]), "+f"(d[2]), "+f"(d[3])
        : "r"(a[0]), "r"(a[2]), "r"(a[1]), "r"(a[3]), "r"(b[0]), "r"(b[1]));
}
__device__ __forceinline__ void cpasync16(uint32_t dst, const void* src) {
    asm volatile("cp.async.cg.shared.global [%0], [%1], 16;" :: "r"(dst), "l"(src) : "memory");
}
__device__ __forceinline__ uint32_t tf32u(float v) {
    uint32_t o;
    asm("cvt.rna.tf32.f32 %0, %1;" : "=r"(o) : "f"(v));
    return o;
}
__device__ __forceinline__ uint32_t tf32b(uint32_t bits) {
    return tf32u(__uint_as_float(bits));
}

// ---------- fp32 -> tf32-rounded fp32 (x only; w rounded in-gemm) ----------
__global__ void round_x(const float* __restrict__ src) {
    int i = blockIdx.x * blockDim.x + threadIdx.x;  // < 262144
    float4 v = reinterpret_cast<const float4*>(src)[i];
    uint4 o{tf32u(v.x), tf32u(v.y), tf32u(v.z), tf32u(v.w)};
    reinterpret_cast<uint4*>(g_x32)[i] = o;
}

// ---------- split-K reduce: out = p0 + p1 + bias ----------
__global__ void reduce_out(const float* __restrict__ bias, float* __restrict__ out) {
    int i = blockIdx.x * blockDim.x + threadIdx.x;  // < 262144 float4s
    float4 p0 = reinterpret_cast<const float4*>(g_part)[i];
    float4 p1 = reinterpret_cast<const float4*>(g_part + 1048576)[i];
    int col4 = i & 2047;
    float4 bb = reinterpret_cast<const float4*>(bias)[col4];
    float4 o{p0.x + p1.x + bb.x, p0.y + p1.y + bb.y,
             p0.z + p1.z + bb.z, p0.w + p1.w + bb.w};
    reinterpret_cast<float4*>(out)[i] = o;
}

// ---------- main GEMM: D[128 x 64] per CTA, per-CTA K = 4096, tf32, chunk=64 ----------
__global__ void __launch_bounds__(THREADS, 2)
ga_gemm(const float* __restrict__ w) {
    // dynamic smem: A0[32K] A1[32K] B0[16K] B1[16K] = 96KB (rows of 64 fp32 = 256B)
    extern __shared__ __align__(1024) uint8_t smem[];
    const int tid = threadIdx.x, wid = tid >> 5, lid = tid & 31;
    const int bx = blockIdx.x & 127, kh = blockIdx.x >> 7;
    const int wm = wid >> 1, wn = wid & 1;  // 4(M) x 2(N) warp grid, warp tile 32x32
    const int kbase = kh * 4096;

    const uint32_t base = smem_u32(smem);
    const uint32_t sA[2] = {base, base + 32768};
    const uint32_t sB[2] = {base + 65536, base + 81920};

    // ---- B-build constants: thread -> row j (n-index), 16 dest k-cols (one blade group) ----
    const int j = tid >> 2, sub = tid & 3;            // j: 0..63 rows, sub: which 16-col group
    const int kk = (bx * 64 + j) & 15;                // blade index of this B row
    const int u = (bx * 64 + j) >> 4;                 // unit index
    const int kkhi = kk >> 2, kb01 = kk & 3;
    uint32_t msk[16];
#pragma unroll
    for (int i = 0; i < 16; i++)
        msk[i] = sign_neg(i, i ^ kk) ? 0x80000000u : 0u;
    const uint32_t brow = (uint32_t)(j * 256);
    const int j7 = j & 7;
    const float* wthread = w + u * 8192 + kbase + sub * 16;

    // ---- A cp.async addressing: 2048 x 16B blocks, 8 per thread (linear in q) ----
    const int r0 = tid >> 4, bblk = tid & 15;
    const int agoff0 = r0 * 8192 + kbase + bblk * 4;              // + q*16*8192
    const uint32_t aswz0 = (uint32_t)(r0 * 256 + ((bblk ^ (r0 & 7)) * 16));  // + q*4096

    // ---- fragment row bases + shared swizzle recompute constants ----
    const int fr = ((lid >> 4) & 1) * 8 + (lid & 7);
    const uint32_t Arow0 = (uint32_t)((wm * 32 + fr) * 256);
    const uint32_t Arow1 = (uint32_t)((wm * 32 + 16 + fr) * 256);
    const uint32_t Brow0 = (uint32_t)((wn * 32 + fr) * 256);
    const uint32_t Brow1 = (uint32_t)((wn * 32 + 16 + fr) * 256);
    const uint32_t c1 = (uint32_t)(lid & 6);
    const uint32_t c0 = (uint32_t)(((lid >> 3) & 1) ^ (lid & 1));

    float d[2][4][4];
#pragma unroll
    for (int a = 0; a < 2; a++)
#pragma unroll
        for (int b = 0; b < 4; b++)
#pragma unroll
            for (int c = 0; c < 4; c++) d[a][b][c] = 0.f;

    // load w RAW (bits only — consumed next iteration, latency hides under compute)
    uint4 V[4];
    auto load_w = [&](int koff) {
#pragma unroll
        for (int q = 0; q < 4; q++)
            V[q] = *reinterpret_cast<const uint4*>(wthread + koff + ((q ^ kkhi) << 2));
    };

    // ---- prologue: stage chunk 0 ----
#pragma unroll
    for (int q = 0; q < 8; q++)
        cpasync16(sA[0] + aswz0 + q * 4096, g_x32 + agoff0 + q * (16 * 8192));
    asm volatile("cp.async.commit_group;" ::: "memory");
    load_w(0);

    for (int c = 0; c < NCHUNK; c++) {
        const int cur = c & 1;
        asm volatile("cp.async.wait_group 0;" ::: "memory");
        // ---- B tile: tf32-round (deferred), permute low blade bits, sign-XOR, store ----
        {
            const uint32_t bb = sB[cur] + brow;
#pragma unroll
            for (int dq = 0; dq < 4; dq++) {
                uint4 o;
                o.x = tf32b(V[dq].x); o.y = tf32b(V[dq].y);
                o.z = tf32b(V[dq].z); o.w = tf32b(V[dq].w);
                if (kb01 & 1) {  // swap adjacent components
                    uint32_t t;
                    t = o.x; o.x = o.y; o.y = t;  t = o.z; o.z = o.w; o.w = t;
                }
                if (kb01 & 2) {  // swap component pairs
                    uint32_t t;
                    t = o.x; o.x = o.z; o.z = t;  t = o.y; o.y = o.w; o.w = t;
                }
                o.x ^= msk[4 * dq + 0]; o.y ^= msk[4 * dq + 1];
                o.z ^= msk[4 * dq + 2]; o.w ^= msk[4 * dq + 3];
                const uint32_t addr = bb + (uint32_t)(((4 * sub + dq) ^ j7) * 16);
                asm volatile("st.shared.v4.b32 [%0], {%1,%2,%3,%4};"
                             :: "r"(addr), "r"(o.x), "r"(o.y), "r"(o.z), "r"(o.w) : "memory");
            }
        }
        __syncthreads();
        // ---- prefetch chunk c+1 ----
        if (c + 1 < NCHUNK) {
            const int koffn = (c + 1) * 64;
#pragma unroll
            for (int q = 0; q < 8; q++)
                cpasync16(sA[cur ^ 1] + aswz0 + q * 4096,
                          g_x32 + agoff0 + koffn + q * (16 * 8192));
            asm volatile("cp.async.commit_group;" ::: "memory");
            load_w(koffn);
        }
        // ---- compute: 8 k-steps (k8 each) x (2 m-tiles x 4 n-tiles) ----
#pragma unroll
        for (int ks = 0; ks < 8; ks++) {
            const uint32_t p = ((((uint32_t)(2 * ks) ^ c1) | c0) << 4);
            uint32_t A0[4], A1[4], Bq0[4], Bq1[4];
            ldsm4(A0[0], A0[1], A0[2], A0[3], sA[cur] + Arow0 + p);
            ldsm4(A1[0], A1[1], A1[2], A1[3], sA[cur] + Arow1 + p);
            ldsm4(Bq0[0], Bq0[1], Bq0[2], Bq0[3], sB[cur] + Brow0 + p);
            ldsm4(Bq1[0], Bq1[1], Bq1[2], Bq1[3], sB[cur] + Brow1 + p);
            mma_tf32(d[0][0], A0, Bq0 + 0);
            mma_tf32(d[0][1], A0, Bq0 + 2);
            mma_tf32(d[0][2], A0, Bq1 + 0);
            mma_tf32(d[0][3], A0, Bq1 + 2);
            mma_tf32(d[1][0], A1, Bq0 + 0);
            mma_tf32(d[1][1], A1, Bq0 + 2);
            mma_tf32(d[1][2], A1, Bq1 + 0);
            mma_tf32(d[1][3], A1, Bq1 + 2);
        }
    }

    // ---- epilogue: partial D -> g_part[kh] (bias added in reduce) ----
    float* pout = g_part + (size_t)kh * 1048576;
#pragma unroll
    for (int mt = 0; mt < 2; mt++) {
        const int m0 = wm * 32 + mt * 16 + (lid >> 2);
#pragma unroll
        for (int nt = 0; nt < 4; nt++) {
            const int nc = bx * 64 + wn * 32 + nt * 8 + 2 * (lid & 3);
            float2 v0{d[mt][nt][0], d[mt][nt][1]};
            float2 v1{d[mt][nt][2], d[mt][nt][3]};
            *reinterpret_cast<float2*>(pout + (size_t)m0 * 8192 + nc) = v0;
            *reinterpret_cast<float2*>(pout + (size_t)(m0 + 8) * 8192 + nc) = v1;
        }
    }
}

extern "C" void kernel_launch(void* const* d_in, const int* in_sizes, int n_in,
                              void* d_out, int out_size) {
    // Dispatch inputs by element count (robust to metadata ordering):
    //   x: 1048576, w: 4194304, b: 8192, cayley: 4096
    const float* x = nullptr;
    const float* w = nullptr;
    const float* bias = nullptr;
    for (int i = 0; i < n_in; i++) {
        if (in_sizes[i] == 1048576)      x    = (const float*)d_in[i];
        else if (in_sizes[i] == 4194304) w    = (const float*)d_in[i];
        else if (in_sizes[i] == 8192)    bias = (const float*)d_in[i];
    }
    float* out = (float*)d_out;

    static bool configured = false;
    if (!configured) {
        cudaFuncSetAttribute(ga_gemm, cudaFuncAttributeMaxDynamicSharedMemorySize, 98304);
        configured = true;
    }

    round_x<<<1024, 256>>>(x);
    ga_gemm<<<256, THREADS, 98304>>>(w);
    reduce_out<<<1024, 256>>>(bias, out);
}

// round 17
// speedup vs baseline: 1.5168x; 1.5168x over previous
#include <cuda_runtime.h>
#include <cuda_bf16.h>
#include <cstdint>

#define THREADS 256
#define NCHUNK  128   // per-CTA K = 4096, chunk = 32 fp32 (split-K = 2)

__device__ __align__(256) float g_x32[128 * 8192];      // tf32-rounded x
__device__ __align__(256) float g_part[2 * 128 * 8192]; // split-K partials

__device__ __forceinline__ uint32_t smem_u32(const void* p) {
    uint32_t a;
    asm("{ .reg .u64 t; cvta.to.shared.u64 t, %1; cvt.u32.u64 %0, t; }" : "=r"(a) : "l"(p));
    return a;
}
__device__ __forceinline__ int sign_neg(int a, int b) {  // 1 if e_a*e_b negative
    int t = a >> 1, c = 0;
    while (t) { c += __popc(t & b); t >>= 1; }
    return c & 1;
}
__device__ __forceinline__ void ldsm4(uint32_t& r0, uint32_t& r1, uint32_t& r2, uint32_t& r3,
                                      uint32_t addr) {
    asm volatile("ldmatrix.sync.aligned.m8n8.x4.shared.b16 {%0,%1,%2,%3}, [%4];"
                 : "=r"(r0), "=r"(r1), "=r"(r2), "=r"(r3) : "r"(addr));
}
// a[] in ldsm matrix order {m0,m1,m2,m3}; mma wants {m0,m2,m1,m3}
__device__ __forceinline__ void mma_tf32(float* d, const uint32_t* a, const uint32_t* b) {
    asm volatile(
        "mma.sync.aligned.m16n8k8.row.col.f32.tf32.tf32.f32 "
        "{%0,%1,%2,%3}, {%4,%5,%6,%7}, {%8,%9}, {%0,%1,%2,%3};"
        : "+f"(d[0]), "+f"(d[1]), "+f"(d[2]), "+f"(d[3])
        : "r"(a[0]), "r"(a[2]), "r"(a[1]), "r"(a[3]), "r"(b[0]), "r"(b[1]));
}
__device__ __forceinline__ void cpasync16(uint32_t dst, const void* src) {
    asm volatile("cp.async.cg.shared.global [%0], [%1], 16;" :: "r"(dst), "l"(src) : "memory");
}
__device__ __forceinline__ uint32_t tf32u(float v) {
    uint32_t o;
    asm("cvt.rna.tf32.f32 %0, %1;" : "=r"(o) : "f"(v));
    return o;
}
__device__ __forceinline__ uint32_t tf32b(uint32_t bits) {
    return tf32u(__uint_as_float(bits));
}

// ---------- fp32 -> tf32-rounded fp32 (x only; w rounded in-gemm) ----------
__global__ void round_x(const float* __restrict__ src) {
    int i = blockIdx.x * blockDim.x + threadIdx.x;  // < 262144
    float4 v = reinterpret_cast<const float4*>(src)[i];
    uint4 o{tf32u(v.x), tf32u(v.y), tf32u(v.z), tf32u(v.w)};
    reinterpret_cast<uint4*>(g_x32)[i] = o;
}

// ---------- split-K reduce: out = p0 + p1 + bias ----------
__global__ void reduce_out(const float* __restrict__ bias, float* __restrict__ out) {
    int i = blockIdx.x * blockDim.x + threadIdx.x;  // < 262144 float4s
    float4 p0 = reinterpret_cast<const float4*>(g_part)[i];
    float4 p1 = reinterpret_cast<const float4*>(g_part + 1048576)[i];
    int col4 = i & 2047;
    float4 bb = reinterpret_cast<const float4*>(bias)[col4];
    float4 o{p0.x + p1.x + bb.x, p0.y + p1.y + bb.y,
             p0.z + p1.z + bb.z, p0.w + p1.w + bb.w};
    reinterpret_cast<float4*>(out)[i] = o;
}

// ---------- main GEMM: D[128 x 64] per CTA, per-CTA K = 4096, tf32, chunk=32,
//            3-stage A pipeline ----------
__global__ void __launch_bounds__(THREADS, 2)
ga_gemm(const float* __restrict__ w) {
    // dynamic smem: A0/A1/A2 [16K each] B0/B1 [8K each] = 64KB
    extern __shared__ __align__(1024) uint8_t smem[];
    const int tid = threadIdx.x, wid = tid >> 5, lid = tid & 31;
    const int bx = blockIdx.x & 127, kh = blockIdx.x >> 7;
    const int wm = wid >> 1, wn = wid & 1;  // 4(M) x 2(N) warp grid, warp tile 32x32
    const int kbase = kh * 4096;

    const uint32_t base = smem_u32(smem);
    const uint32_t sA[3] = {base, base + 16384, base + 32768};
    const uint32_t sB[2] = {base + 49152, base + 57344};

    // ---- B-build constants: thread -> row j = uu*16+kk, 8 dest elements ----
    const int j = tid >> 2, sub = tid & 3;
    const int kk = j & 15, uu = j >> 4;
    const int u = bx * 4 + uu;
    const int hsel = sub & 1, qsel = sub >> 1;
    const int kb01 = kk & 3, kb2 = (kk >> 2) & 1, kb3 = (kk >> 3) & 1;
    const int srcoff = 16 * qsel + 8 * (hsel ^ kb3);
    const int s0 = srcoff + 4 * (0 ^ kb2);
    const int s1 = srcoff + 4 * (1 ^ kb2);
    uint32_t msk[8];
#pragma unroll
    for (int e = 0; e < 8; e++) {
        int i = 8 * hsel + e;
        msk[e] = sign_neg(i, i ^ kk) ? 0x80000000u : 0u;
    }
    const uint32_t sts0 = (uint32_t)(j * 128 + ((2 * sub) ^ (j & 7)) * 16);
    const uint32_t sts1 = (uint32_t)(j * 128 + ((2 * sub + 1) ^ (j & 7)) * 16);
    const float* wbase = w + u * 8192 + kbase;

    // ---- A cp.async addressing: 1024 x 16B blocks, 4 per thread ----
    int agoff[4];
    uint32_t aswz[4];
#pragma unroll
    for (int q = 0; q < 4; q++) {
        int idx = q * 256 + tid;
        int r = idx >> 3, blk = idx & 7;
        agoff[q] = r * 8192 + kbase + blk * 4;  // fp32 elements
        aswz[q] = (uint32_t)(r * 128 + (blk ^ (r & 7)) * 16);
    }

    // ---- ldmatrix address tables (buffer-relative) ----
    uint32_t aoff[2][4], boff[2][4];
#pragma unroll
    for (int mt = 0; mt < 2; mt++)
#pragma unroll
        for (int ks = 0; ks < 4; ks++) {
            int r = wm * 32 + mt * 16 + ((lid >> 4) & 1) * 8 + (lid & 7);
            int blk = 2 * ks + ((lid >> 3) & 1);
            aoff[mt][ks] = (uint32_t)(r * 128 + (blk ^ (r & 7)) * 16);
        }
#pragma unroll
    for (int g = 0; g < 2; g++)
#pragma unroll
        for (int ks = 0; ks < 4; ks++) {
            int n = wn * 32 + g * 16 + ((lid >> 4) & 1) * 8 + (lid & 7);
            int blk = 2 * ks + ((lid >> 3) & 1);
            boff[g][ks] = (uint32_t)(n * 128 + (blk ^ (n & 7)) * 16);
        }

    float d[2][4][4];
#pragma unroll
    for (int a = 0; a < 2; a++)
#pragma unroll
        for (int b = 0; b < 4; b++)
#pragma unroll
            for (int c = 0; c < 4; c++) d[a][b][c] = 0.f;

    // load w RAW (bits only — consumed next iteration's B-build)
    uint4 V0, V1;
    auto load_w = [&](int koff) {
        V0 = *reinterpret_cast<const uint4*>(wbase + koff + s0);
        V1 = *reinterpret_cast<const uint4*>(wbase + koff + s1);
    };
    auto stage_a = [&](int buf, int koff) {
#pragma unroll
        for (int q = 0; q < 4; q++)
            cpasync16(sA[buf] + aswz[q], g_x32 + agoff[q] + koff);
        asm volatile("cp.async.commit_group;" ::: "memory");
    };

    // ---- prologue: stage chunks 0 and 1 (two groups in flight) ----
    stage_a(0, 0);
    stage_a(1, 32);
    load_w(0);

    for (int c = 0; c < NCHUNK; c++) {
        const int curA = c % 3, curB = c & 1;
        // ---- B tile (register deps only): tf32-round, permute, sign-XOR, store ----
        // WAR on B[curB] protected by the sync two iterations ago.
        {
            uint4 o0, o1;
            o0.x = tf32b(V0.x); o0.y = tf32b(V0.y); o0.z = tf32b(V0.z); o0.w = tf32b(V0.w);
            o1.x = tf32b(V1.x); o1.y = tf32b(V1.y); o1.z = tf32b(V1.z); o1.w = tf32b(V1.w);
            if (kb01 & 1) {
                uint32_t t;
                t = o0.x; o0.x = o0.y; o0.y = t;  t = o0.z; o0.z = o0.w; o0.w = t;
                t = o1.x; o1.x = o1.y; o1.y = t;  t = o1.z; o1.z = o1.w; o1.w = t;
            }
            if (kb01 & 2) {
                uint32_t t;
                t = o0.x; o0.x = o0.z; o0.z = t;  t = o0.y; o0.y = o0.w; o0.w = t;
                t = o1.x; o1.x = o1.z; o1.z = t;  t = o1.y; o1.y = o1.w; o1.w = t;
            }
            o0.x ^= msk[0]; o0.y ^= msk[1]; o0.z ^= msk[2]; o0.w ^= msk[3];
            o1.x ^= msk[4]; o1.y ^= msk[5]; o1.z ^= msk[6]; o1.w ^= msk[7];
            uint8_t* bbuf = smem + 49152 + (curB << 13);
            *reinterpret_cast<uint4*>(bbuf + sts0) = o0;
            *reinterpret_cast<uint4*>(bbuf + sts1) = o1;
        }
        // ---- A[c] ready (allow 1 group — chunk c+1 — still in flight) ----
        asm volatile("cp.async.wait_group 1;" ::: "memory");
        __syncthreads();
        // ---- prefetch: A for chunk c+2, w for chunk c+1 ----
        if (c + 2 < NCHUNK) stage_a((c + 2) % 3, (c + 2) * 32);
        else asm volatile("cp.async.commit_group;" ::: "memory");  // keep group count in step
        if (c + 1 < NCHUNK) load_w((c + 1) * 32);
        // ---- compute: 4 k-steps (k8 each) x (2 m-tiles x 4 n-tiles) ----
#pragma unroll
        for (int ks = 0; ks < 4; ks++) {
            uint32_t A0[4], A1[4], Bq0[4], Bq1[4];
            ldsm4(A0[0], A0[1], A0[2], A0[3], sA[curA] + aoff[0][ks]);
            ldsm4(A1[0], A1[1], A1[2], A1[3], sA[curA] + aoff[1][ks]);
            ldsm4(Bq0[0], Bq0[1], Bq0[2], Bq0[3], sB[curB] + boff[0][ks]);
            ldsm4(Bq1[0], Bq1[1], Bq1[2], Bq1[3], sB[curB] + boff[1][ks]);
            mma_tf32(d[0][0], A0, Bq0 + 0);
            mma_tf32(d[0][1], A0, Bq0 + 2);
            mma_tf32(d[0][2], A0, Bq1 + 0);
            mma_tf32(d[0][3], A0, Bq1 + 2);
            mma_tf32(d[1][0], A1, Bq0 + 0);
            mma_tf32(d[1][1], A1, Bq0 + 2);
            mma_tf32(d[1][2], A1, Bq1 + 0);
            mma_tf32(d[1][3], A1, Bq1 + 2);
        }
    }

    // ---- epilogue: partial D -> g_part[kh] (bias added in reduce) ----
    float* pout = g_part + (size_t)kh * 1048576;
#pragma unroll
    for (int mt = 0; mt < 2; mt++) {
        const int m0 = wm * 32 + mt * 16 + (lid >> 2);
#pragma unroll
        for (int nt = 0; nt < 4; nt++) {
            const int nc = bx * 64 + wn * 32 + nt * 8 + 2 * (lid & 3);
            float2 v0{d[mt][nt][0], d[mt][nt][1]};
            float2 v1{d[mt][nt][2], d[mt][nt][3]};
            *reinterpret_cast<float2*>(pout + (size_t)m0 * 8192 + nc) = v0;
            *reinterpret_cast<float2*>(pout + (size_t)(m0 + 8) * 8192 + nc) = v1;
        }
    }
}

extern "C" void kernel_launch(void* const* d_in, const int* in_sizes, int n_in,
                              void* d_out, int out_size) {
    // Dispatch inputs by element count (robust to metadata ordering):
    //   x: 1048576, w: 4194304, b: 8192, cayley: 4096
    const float* x = nullptr;
    const float* w = nullptr;
    const float* bias = nullptr;
    for (int i = 0; i < n_in; i++) {
        if (in_sizes[i] == 1048576)      x    = (const float*)d_in[i];
        else if (in_sizes[i] == 4194304) w    = (const float*)d_in[i];
        else if (in_sizes[i] == 8192)    bias = (const float*)d_in[i];
    }
    float* out = (float*)d_out;

    static bool configured = false;
    if (!configured) {
        cudaFuncSetAttribute(ga_gemm, cudaFuncAttributeMaxDynamicSharedMemorySize, 65536);
        configured = true;
    }

    round_x<<<1024, 256>>>(x);
    ga_gemm<<<256, THREADS, 65536>>>(w);
    reduce_out<<<1024, 256>>>(bias, out);
}